// round 13
// baseline (speedup 1.0000x reference)
#include <cuda_runtime.h>
#include <cuda_fp16.h>
#include <cstdint>

// Fused NonLinearReadoutLayer via mma.sync.m16n8k16 (fp16 in, fp32 accum).
// Round 13: persistent kernel with FIXED one-pass v extraction (lane owns 48B
// = 4 m-triples => full 128-column coverage); ch0->bufA, ch1->bufB, ch2
// re-extracted from L2 after ch0 frees bufA. No register carry. Weights
// resident; work-stealing; no CTA barriers after init.

#define DIN     512
#define THREADS 384
#define NSM     152

#define PA  136   // halves
#define PB  136
#define PW2 40

// smem layout (bytes)
#define OFF_WG  0u          // w1s[1] (gates B)     34816
#define OFF_WA  34816u      // w1s[0] (act B)       34816
#define OFF_WV  69632u      // w1v                  34816
#define OFF_W2  104448u     // w2s|w2v              10240
#define OFF_AW  114688u     // 12 warps x 2 buffers x 4352 B
#define SMEM_BYTES 219136u

__device__ __align__(16) __half g_w1s[2][128 * PB];
__device__ __align__(16) __half g_w1v[128 * PB];
__device__ __align__(16) __half g_w2[128 * PW2];
__device__ int g_ctr;

// ---------------------------------------------------------------- helpers
__device__ __forceinline__ uint32_t smem_u32(const void* p) {
    uint32_t a;
    asm("{ .reg .u64 t; cvta.to.shared.u64 t, %1; cvt.u32.u64 %0, t; }"
        : "=r"(a) : "l"(p));
    return a;
}
__device__ __forceinline__ uint32_t h2u(__half2 h) {
    return *reinterpret_cast<uint32_t*>(&h);
}
__device__ __forceinline__ float sigf(float x) {
    return __fdividef(1.0f, 1.0f + __expf(-x));
}
#define CP16(d, s) \
    asm volatile("cp.async.cg.shared.global [%0], [%1], 16;" \
                 :: "r"(d), "l"(s))
#define CP_COMMIT() asm volatile("cp.async.commit_group;" ::: "memory")
#define CP_WAIT(n)  asm volatile("cp.async.wait_group %0;" :: "n"(n) : "memory")

__device__ __forceinline__ void cp_bulk(uint32_t dst, const void* src, int n16,
                                        int tid) {
    const char* s = (const char*)src;
    for (int i = tid; i < n16; i += THREADS) CP16(dst + i * 16, s + (long)i * 16);
}

__device__ __forceinline__ void ldsm4(uint32_t* r, uint32_t addr) {
    asm volatile("ldmatrix.sync.aligned.m8n8.x4.shared.b16 {%0,%1,%2,%3}, [%4];"
                 : "=r"(r[0]), "=r"(r[1]), "=r"(r[2]), "=r"(r[3]) : "r"(addr));
}
__device__ __forceinline__ void ldsm4t(uint32_t* r, uint32_t addr) {
    asm volatile("ldmatrix.sync.aligned.m8n8.x4.trans.shared.b16 {%0,%1,%2,%3}, [%4];"
                 : "=r"(r[0]), "=r"(r[1]), "=r"(r[2]), "=r"(r[3]) : "r"(addr));
}
__device__ __forceinline__ void mma16816(float* c, const uint32_t* a, const uint32_t* b) {
    asm volatile(
        "mma.sync.aligned.m16n8k16.row.col.f32.f16.f16.f32 "
        "{%0,%1,%2,%3}, {%4,%5,%6,%7}, {%8,%9}, {%0,%1,%2,%3};"
        : "+f"(c[0]), "+f"(c[1]), "+f"(c[2]), "+f"(c[3])
        : "r"(a[0]), "r"(a[1]), "r"(a[2]), "r"(a[3]), "r"(b[0]), "r"(b[1]));
}
__device__ __forceinline__ void ldsmA(uint32_t* af, uint32_t aAddr) {
    #pragma unroll
    for (int k = 0; k < 8; ++k) ldsm4(af + 4 * k, aAddr + k * 32);
}
__device__ __forceinline__ void gemm_rA4(float (*acc)[4], const uint32_t* af,
                                         uint32_t bAddr, uint32_t pbB) {
    #pragma unroll
    for (int k = 0; k < 8; ++k) {
        #pragma unroll
        for (int g = 0; g < 4; ++g) {
            uint32_t b[4];
            ldsm4t(b, bAddr + k * 16 * pbB + g * 32);
            mma16816(acc[2 * g],     af + 4 * k, b);
            mma16816(acc[2 * g + 1], af + 4 * k, b + 2);
        }
    }
}
__device__ __forceinline__ void gemm_rA1(float (*acc)[4], const uint32_t* af,
                                         uint32_t bAddr, uint32_t pbB) {
    #pragma unroll
    for (int k = 0; k < 8; ++k) {
        uint32_t b[4];
        ldsm4t(b, bAddr + k * 16 * pbB);
        mma16816(acc[0], af + 4 * k, b);
        mma16816(acc[1], af + 4 * k, b + 2);
    }
}

// ---------------------------------------------------------------- prep (weights)
__global__ void prep_w(const float* __restrict__ w1s, const float* __restrict__ w1v,
                       const float* __restrict__ w2s, const float* __restrict__ w2v) {
    int idx = blockIdx.x * blockDim.x + threadIdx.x;
    int stride = gridDim.x * blockDim.x;
    if (idx == 0) g_ctr = 0;          // reset work counter (graph replay safe)
    for (int i = idx; i < 2 * 128 * 128; i += stride) {
        int h = i >> 14, k = (i >> 7) & 127, n = i & 127;
        g_w1s[h][k * PB + n] = __float2half_rn(w1s[k * 256 + h * 128 + n]);
    }
    for (int i = idx; i < 128 * 128; i += stride)
        g_w1v[(i >> 7) * PB + (i & 127)] = __float2half_rn(w1v[i]);
    for (int i = idx; i < 128 * 16; i += stride) {
        int k = i >> 4, n = i & 15;
        g_w2[k * PW2 + n]      = __float2half_rn(w2s[i]);
        g_w2[k * PW2 + 16 + n] = __float2half_rn(w2v[i]);
    }
}

// ---------------------------------------------------------------- main (persistent)
__global__ void __launch_bounds__(THREADS, 1)
nlro(const float* __restrict__ x, float* __restrict__ out, int N) {
    extern __shared__ char sm[];
    const uint32_t smb = smem_u32(sm);
    const int tid = threadIdx.x, lane = tid & 31, wid = tid >> 5;
    const float INV = 0.08838834764831845f;

    const int cpair = 2 * (lane & 3);
    const int l16 = lane & 15, lhi = lane >> 4;

    const uint32_t bufA = smb + OFF_AW + wid * 8704u;
    char* bufAp = sm + OFF_AW + wid * 8704u;
    char* bufBp = bufAp + 4352;
    const uint32_t aOffA = bufA + (l16 * PA + lhi * 8) * 2;
    const uint32_t aOffB = aOffA + 4352u;
    const uint32_t bG   = smb + OFF_WG + (l16 * PB + lhi * 8) * 2;
    const uint32_t bA   = smb + OFF_WA + (l16 * PB + lhi * 8) * 2;
    const uint32_t bV   = smb + OFF_WV + (l16 * PB + lhi * 8) * 2;
    const uint32_t bOffS = smb + OFF_W2 + (l16 * PW2 + lhi * 8) * 2;
    const uint32_t bOffV = bOffS + 32;

    // ---- one-time weight residency (only CTA barrier in the kernel) ----
    cp_bulk(smb + OFF_WG, &g_w1s[1][0], 2176, tid);
    cp_bulk(smb + OFF_WA, &g_w1s[0][0], 2176, tid);
    cp_bulk(smb + OFF_WV, g_w1v, 2176, tid);
    cp_bulk(smb + OFF_W2, g_w2, 640, tid);
    CP_COMMIT();
    CP_WAIT(0);
    __syncthreads();

    const int total = (N + 15) >> 4;

    for (;;) {
        int s = 0;
        if (lane == 0) s = atomicAdd(&g_ctr, 1);
        s = __shfl_sync(0xFFFFFFFFu, s, 0);
        if (s >= total) break;

        const long row0g = (long)s * 16;

        // ---- stage x_s -> bufA (coalesced 512B rows, warp-local) ----
        #pragma unroll 4
        for (int it = 0; it < 16; ++it) {
            long grow = row0g + it;
            bool ok = grow < N;
            const float4* p = (const float4*)(x + grow * DIN);
            float4 v = ok ? p[lane] : make_float4(0, 0, 0, 0);
            uint2 u;
            u.x = h2u(__floats2half2_rn(v.x, v.y));
            u.y = h2u(__floats2half2_rn(v.z, v.w));
            *(uint2*)(bufAp + (it * PA + lane * 4) * 2) = u;
        }
        __syncwarp();

        uint32_t af[32];
        ldsmA(af, aOffA);              // x_s fragments -> regs; bufA free
        __syncwarp();

        // ---- one-pass v extraction: lane owns m=4l..4l+3 (48B); ch0->A, ch1->B
        #pragma unroll 2
        for (int it = 0; it < 16; ++it) {
            long grow = row0g + it;
            bool ok = grow < N;
            const float4* p = (const float4*)(x + grow * DIN + 128) + 3 * lane;
            float4 q0 = ok ? p[0] : make_float4(0, 0, 0, 0);
            float4 q1 = ok ? p[1] : make_float4(0, 0, 0, 0);
            float4 q2 = ok ? p[2] : make_float4(0, 0, 0, 0);
            uint32_t off = (uint32_t)(it * PA + lane * 4) * 2;
            uint2 u0, u1;
            u0.x = h2u(__floats2half2_rn(q0.x, q0.w));   // c0: m=4l, 4l+1
            u0.y = h2u(__floats2half2_rn(q1.z, q2.y));   //     m=4l+2, 4l+3
            u1.x = h2u(__floats2half2_rn(q0.y, q1.x));   // c1
            u1.y = h2u(__floats2half2_rn(q1.w, q2.z));
            *(uint2*)(bufAp + off) = u0;
            *(uint2*)(bufBp + off) = u1;
        }

        // ---- gates: sigmoid(h_s[:,128:]) -> registers ----
        uint32_t gfa[16], gfb[16];
        #pragma unroll
        for (int h = 0; h < 2; ++h) {
            float acc[8][4] = {};
            gemm_rA4(acc, af, bG + h * 128, PB * 2);
            #pragma unroll
            for (int tt = 0; tt < 8; ++tt) {
                gfa[h * 8 + tt] = h2u(__floats2half2_rn(sigf(INV * acc[tt][0]),
                                                        sigf(INV * acc[tt][1])));
                gfb[h * 8 + tt] = h2u(__floats2half2_rn(sigf(INV * acc[tt][2]),
                                                        sigf(INV * acc[tt][3])));
            }
        }

        // ---- act: silu(h_s[:,:128]) -> A-fragments ----
        uint32_t afrag[32];
        #pragma unroll
        for (int h = 0; h < 2; ++h) {
            float acc[8][4] = {};
            gemm_rA4(acc, af, bA + h * 128, PB * 2);
            #pragma unroll
            for (int tt = 0; tt < 8; tt += 2) {
                int kb = h * 4 + (tt >> 1);
                float a0 = INV * acc[tt][0],     a1 = INV * acc[tt][1];
                float a2 = INV * acc[tt][2],     a3 = INV * acc[tt][3];
                float a4 = INV * acc[tt + 1][0], a5 = INV * acc[tt + 1][1];
                float a6 = INV * acc[tt + 1][2], a7 = INV * acc[tt + 1][3];
                a0 *= sigf(a0); a1 *= sigf(a1); a2 *= sigf(a2); a3 *= sigf(a3);
                a4 *= sigf(a4); a5 *= sigf(a5); a6 *= sigf(a6); a7 *= sigf(a7);
                afrag[4 * kb + 0] = h2u(__floats2half2_rn(a0, a1));
                afrag[4 * kb + 1] = h2u(__floats2half2_rn(a2, a3));
                afrag[4 * kb + 2] = h2u(__floats2half2_rn(a4, a5));
                afrag[4 * kb + 3] = h2u(__floats2half2_rn(a6, a7));
            }
        }

        // ---- L2-s; write out_s ----
        {
            float acc2[2][4] = {};
            gemm_rA1(acc2, afrag, bOffS, PW2 * 2);
            long gr0 = row0g + (lane >> 2), gr1 = gr0 + 8;
            if (gr0 < N) {
                *(float2*)&out[gr0 * 64 + cpair]     = make_float2(INV * acc2[0][0], INV * acc2[0][1]);
                *(float2*)&out[gr0 * 64 + cpair + 8] = make_float2(INV * acc2[1][0], INV * acc2[1][1]);
            }
            if (gr1 < N) {
                *(float2*)&out[gr1 * 64 + cpair]     = make_float2(INV * acc2[0][2], INV * acc2[0][3]);
                *(float2*)&out[gr1 * 64 + cpair + 8] = make_float2(INV * acc2[1][2], INV * acc2[1][3]);
            }
        }

        // ---- per-channel: G1-v -> gate (regs) -> L2-v (all warp-local) ----
        float vout[24];
        #define VOUT(r, g, k, c) ((((r) * 2 + (g)) * 2 + (k)) * 3 + (c))
        #pragma unroll
        for (int c = 0; c < 3; ++c) {
            if (c == 0) {
                __syncwarp();              // extraction STS visible warp-wide
                ldsmA(af, aOffA);          // ch0 -> regs; bufA free again
                __syncwarp();
                // re-extract ch2 into bufA (rows L2-resident from pass above)
                #pragma unroll 2
                for (int it = 0; it < 16; ++it) {
                    long grow = row0g + it;
                    bool ok = grow < N;
                    const float4* p = (const float4*)(x + grow * DIN + 128) + 3 * lane;
                    float4 q0 = ok ? p[0] : make_float4(0, 0, 0, 0);
                    float4 q1 = ok ? p[1] : make_float4(0, 0, 0, 0);
                    float4 q2 = ok ? p[2] : make_float4(0, 0, 0, 0);
                    uint2 u2;
                    u2.x = h2u(__floats2half2_rn(q0.z, q1.y));   // c2: m=4l, 4l+1
                    u2.y = h2u(__floats2half2_rn(q2.x, q2.w));   //     m=4l+2, 4l+3
                    *(uint2*)(bufAp + (uint32_t)(it * PA + lane * 4) * 2) = u2;
                }
            } else if (c == 1) {
                ldsmA(af, aOffB);          // ch1
            } else {
                __syncwarp();              // ch2 STS visible warp-wide
                ldsmA(af, aOffA);
            }

            #pragma unroll
            for (int h = 0; h < 2; ++h) {
                float acc[8][4] = {};
                gemm_rA4(acc, af, bV + h * 128, PB * 2);
                #pragma unroll
                for (int tt = 0; tt < 8; tt += 2) {
                    int kb = h * 4 + (tt >> 1);
                    float2 g00 = __half22float2(*(__half2*)&gfa[h * 8 + tt]);
                    float2 g01 = __half22float2(*(__half2*)&gfb[h * 8 + tt]);
                    float2 g10 = __half22float2(*(__half2*)&gfa[h * 8 + tt + 1]);
                    float2 g11 = __half22float2(*(__half2*)&gfb[h * 8 + tt + 1]);
                    float a0 = INV * acc[tt][0] * g00.x,     a1 = INV * acc[tt][1] * g00.y;
                    float a2 = INV * acc[tt][2] * g01.x,     a3 = INV * acc[tt][3] * g01.y;
                    float a4 = INV * acc[tt + 1][0] * g10.x, a5 = INV * acc[tt + 1][1] * g10.y;
                    float a6 = INV * acc[tt + 1][2] * g11.x, a7 = INV * acc[tt + 1][3] * g11.y;
                    afrag[4 * kb + 0] = h2u(__floats2half2_rn(a0, a1));
                    afrag[4 * kb + 1] = h2u(__floats2half2_rn(a2, a3));
                    afrag[4 * kb + 2] = h2u(__floats2half2_rn(a4, a5));
                    afrag[4 * kb + 3] = h2u(__floats2half2_rn(a6, a7));
                }
            }
            {
                float acc2[2][4] = {};
                gemm_rA1(acc2, afrag, bOffV, PW2 * 2);
                vout[VOUT(0, 0, 0, c)] = INV * acc2[0][0];
                vout[VOUT(0, 0, 1, c)] = INV * acc2[0][1];
                vout[VOUT(1, 0, 0, c)] = INV * acc2[0][2];
                vout[VOUT(1, 0, 1, c)] = INV * acc2[0][3];
                vout[VOUT(0, 1, 0, c)] = INV * acc2[1][0];
                vout[VOUT(0, 1, 1, c)] = INV * acc2[1][1];
                vout[VOUT(1, 1, 0, c)] = INV * acc2[1][2];
                vout[VOUT(1, 1, 1, c)] = INV * acc2[1][3];
            }
        }

        // ---- write out_v ----
        #pragma unroll
        for (int r = 0; r < 2; ++r) {
            long gr = row0g + (lane >> 2) + r * 8;
            if (gr < N) {
                float* op = out + gr * 64 + 16;
                #pragma unroll
                for (int g = 0; g < 2; ++g) {
                    int kb = cpair + 8 * g;
                    float* q = op + kb * 3;
                    *(float2*)(q + 0) = make_float2(vout[VOUT(r, g, 0, 0)], vout[VOUT(r, g, 0, 1)]);
                    *(float2*)(q + 2) = make_float2(vout[VOUT(r, g, 0, 2)], vout[VOUT(r, g, 1, 0)]);
                    *(float2*)(q + 4) = make_float2(vout[VOUT(r, g, 1, 1)], vout[VOUT(r, g, 1, 2)]);
                }
            }
        }
        #undef VOUT
    }
}

// ---------------------------------------------------------------- launch
extern "C" void kernel_launch(void* const* d_in, const int* in_sizes, int n_in,
                              void* d_out, int out_size) {
    const float* x   = (const float*)d_in[0];
    const float* w1s = (const float*)d_in[1];
    const float* w1v = (const float*)d_in[2];
    const float* w2s = (const float*)d_in[3];
    const float* w2v = (const float*)d_in[4];
    float* out = (float*)d_out;

    const int N = in_sizes[0] / DIN;

    prep_w<<<132, 256>>>(w1s, w1v, w2s, w2v);

    cudaFuncSetAttribute(nlro, cudaFuncAttributeMaxDynamicSharedMemorySize,
                         SMEM_BYTES);
    nlro<<<NSM, THREADS, SMEM_BYTES>>>(x, out, N);
}

// round 14
// speedup vs baseline: 1.3914x; 1.3914x over previous
#include <cuda_runtime.h>
#include <cuda_fp16.h>
#include <cstdint>

// Fused NonLinearReadoutLayer via mma.sync.m16n8k16 (fp16 in, fp32 accum).
// Round 14: persistent kernel with producer/consumer warp specialization.
// Warps 0-1 per CTA extract v-channel tiles into g_xv (work-stolen, flagged),
// then join the 14 consumer warps running the proven R11 strip loop
// (cp.async channel prefetch, register gates, global work-stealing).

#define DIN     512
#define THREADS 512
#define NSM     152
#define MAX_TILES 1564

#define PA  136   // halves
#define PB  136
#define PW2 40

// smem layout (bytes)
#define OFF_WG  0u          // w1s[1] (gates B)     34816
#define OFF_WA  34816u      // w1s[0] (act B)       34816
#define OFF_WV  69632u      // w1v                  34816
#define OFF_W2  104448u     // w2s|w2v              10240
#define OFF_AW  114688u     // 16 per-warp A buffers, 4352 B each
#define SMEM_BYTES 184320u

__device__ __align__(16) __half g_w1s[2][128 * PB];
__device__ __align__(16) __half g_w1v[128 * PB];
__device__ __align__(16) __half g_w2[128 * PW2];
__device__ __align__(16) __half g_xv[(long)MAX_TILES * 3 * 128 * PA];
__device__ int g_ctr;       // consumer strip counter
__device__ int g_tctr;      // producer tile counter
__device__ int g_flag[MAX_TILES];

// ---------------------------------------------------------------- helpers
__device__ __forceinline__ uint32_t smem_u32(const void* p) {
    uint32_t a;
    asm("{ .reg .u64 t; cvta.to.shared.u64 t, %1; cvt.u32.u64 %0, t; }"
        : "=r"(a) : "l"(p));
    return a;
}
__device__ __forceinline__ uint32_t h2u(__half2 h) {
    return *reinterpret_cast<uint32_t*>(&h);
}
__device__ __forceinline__ float sigf(float x) {
    return __fdividef(1.0f, 1.0f + __expf(-x));
}
#define CP16(d, s) \
    asm volatile("cp.async.cg.shared.global [%0], [%1], 16;" \
                 :: "r"(d), "l"(s))
#define CP_COMMIT() asm volatile("cp.async.commit_group;" ::: "memory")
#define CP_WAIT(n)  asm volatile("cp.async.wait_group %0;" :: "n"(n) : "memory")

__device__ __forceinline__ void cp_bulk(uint32_t dst, const void* src, int n16,
                                        int tid) {
    const char* s = (const char*)src;
    for (int i = tid; i < n16; i += THREADS) CP16(dst + i * 16, s + (long)i * 16);
}
__device__ __forceinline__ void cp_warp(uint32_t dst, const void* src, int lane) {
    const char* s = (const char*)src;
    #pragma unroll
    for (int i = lane; i < 272; i += 32) CP16(dst + i * 16, s + (long)i * 16);
}

__device__ __forceinline__ void ldsm4(uint32_t* r, uint32_t addr) {
    asm volatile("ldmatrix.sync.aligned.m8n8.x4.shared.b16 {%0,%1,%2,%3}, [%4];"
                 : "=r"(r[0]), "=r"(r[1]), "=r"(r[2]), "=r"(r[3]) : "r"(addr));
}
__device__ __forceinline__ void ldsm4t(uint32_t* r, uint32_t addr) {
    asm volatile("ldmatrix.sync.aligned.m8n8.x4.trans.shared.b16 {%0,%1,%2,%3}, [%4];"
                 : "=r"(r[0]), "=r"(r[1]), "=r"(r[2]), "=r"(r[3]) : "r"(addr));
}
__device__ __forceinline__ void mma16816(float* c, const uint32_t* a, const uint32_t* b) {
    asm volatile(
        "mma.sync.aligned.m16n8k16.row.col.f32.f16.f16.f32 "
        "{%0,%1,%2,%3}, {%4,%5,%6,%7}, {%8,%9}, {%0,%1,%2,%3};"
        : "+f"(c[0]), "+f"(c[1]), "+f"(c[2]), "+f"(c[3])
        : "r"(a[0]), "r"(a[1]), "r"(a[2]), "r"(a[3]), "r"(b[0]), "r"(b[1]));
}
__device__ __forceinline__ void ldsmA(uint32_t* af, uint32_t aAddr) {
    #pragma unroll
    for (int k = 0; k < 8; ++k) ldsm4(af + 4 * k, aAddr + k * 32);
}
__device__ __forceinline__ void gemm_rA4(float (*acc)[4], const uint32_t* af,
                                         uint32_t bAddr, uint32_t pbB) {
    #pragma unroll
    for (int k = 0; k < 8; ++k) {
        #pragma unroll
        for (int g = 0; g < 4; ++g) {
            uint32_t b[4];
            ldsm4t(b, bAddr + k * 16 * pbB + g * 32);
            mma16816(acc[2 * g],     af + 4 * k, b);
            mma16816(acc[2 * g + 1], af + 4 * k, b + 2);
        }
    }
}
__device__ __forceinline__ void gemm_rA1(float (*acc)[4], const uint32_t* af,
                                         uint32_t bAddr, uint32_t pbB) {
    #pragma unroll
    for (int k = 0; k < 8; ++k) {
        uint32_t b[4];
        ldsm4t(b, bAddr + k * 16 * pbB);
        mma16816(acc[0], af + 4 * k, b);
        mma16816(acc[1], af + 4 * k, b + 2);
    }
}

// ---------------------------------------------------------------- prep (weights + reset)
__global__ void prep_w(const float* __restrict__ w1s, const float* __restrict__ w1v,
                       const float* __restrict__ w2s, const float* __restrict__ w2v) {
    int idx = blockIdx.x * blockDim.x + threadIdx.x;
    int stride = gridDim.x * blockDim.x;
    if (idx == 0) { g_ctr = 0; g_tctr = 0; }
    for (int i = idx; i < MAX_TILES; i += stride) g_flag[i] = 0;
    for (int i = idx; i < 2 * 128 * 128; i += stride) {
        int h = i >> 14, k = (i >> 7) & 127, n = i & 127;
        g_w1s[h][k * PB + n] = __float2half_rn(w1s[k * 256 + h * 128 + n]);
    }
    for (int i = idx; i < 128 * 128; i += stride)
        g_w1v[(i >> 7) * PB + (i & 127)] = __float2half_rn(w1v[i]);
    for (int i = idx; i < 128 * 16; i += stride) {
        int k = i >> 4, n = i & 15;
        g_w2[k * PW2 + n]      = __float2half_rn(w2s[i]);
        g_w2[k * PW2 + 16 + n] = __float2half_rn(w2v[i]);
    }
}

// ---------------------------------------------------------------- main (persistent)
__global__ void __launch_bounds__(THREADS, 1)
nlro(const float* __restrict__ x, float* __restrict__ out, int N) {
    extern __shared__ char sm[];
    const uint32_t smb = smem_u32(sm);
    const int tid = threadIdx.x, lane = tid & 31, wid = tid >> 5;
    const float INV = 0.08838834764831845f;

    const int cpair = 2 * (lane & 3);
    const int l16 = lane & 15, lhi = lane >> 4;

    const uint32_t warpBuf = smb + OFF_AW + wid * 4352u;
    char* warpBufP = sm + OFF_AW + wid * 4352u;
    const uint32_t aOff = warpBuf + (l16 * PA + lhi * 8) * 2;
    const uint32_t bG   = smb + OFF_WG + (l16 * PB + lhi * 8) * 2;
    const uint32_t bA   = smb + OFF_WA + (l16 * PB + lhi * 8) * 2;
    const uint32_t bV   = smb + OFF_WV + (l16 * PB + lhi * 8) * 2;
    const uint32_t bOffS = smb + OFF_W2 + (l16 * PW2 + lhi * 8) * 2;
    const uint32_t bOffV = bOffS + 32;

    // ---- one-time weight residency (only CTA barrier in the kernel) ----
    cp_bulk(smb + OFF_WG, &g_w1s[1][0], 2176, tid);
    cp_bulk(smb + OFF_WA, &g_w1s[0][0], 2176, tid);
    cp_bulk(smb + OFF_WV, g_w1v, 2176, tid);
    cp_bulk(smb + OFF_W2, g_w2, 640, tid);
    CP_COMMIT();
    CP_WAIT(0);
    __syncthreads();

    const int tiles = (N + 127) >> 7;
    const int total = (N + 15) >> 4;

    // ================= producer phase (warps 0-1 of each CTA) =============
    if (wid < 2) {
        for (;;) {
            int t = 0;
            if (lane == 0) t = atomicAdd(&g_tctr, 1);
            t = __shfl_sync(0xFFFFFFFFu, t, 0);
            if (t >= tiles) break;

            const long rbase = (long)t * 128;
            __half* dst0 = &g_xv[((long)t * 3 + 0) * 128 * PA];
            __half* dst1 = &g_xv[((long)t * 3 + 1) * 128 * PA];
            __half* dst2 = &g_xv[((long)t * 3 + 2) * 128 * PA];
            #pragma unroll 4
            for (int row = 0; row < 128; ++row) {
                long grow = rbase + row;
                bool ok = grow < N;
                const float4* p = (const float4*)(x + grow * DIN + 128) + 3 * lane;
                float4 q0 = ok ? p[0] : make_float4(0, 0, 0, 0);
                float4 q1 = ok ? p[1] : make_float4(0, 0, 0, 0);
                float4 q2 = ok ? p[2] : make_float4(0, 0, 0, 0);
                uint32_t off = (uint32_t)row * PA + lane * 4;
                uint2 u0, u1, u2;
                u0.x = h2u(__floats2half2_rn(q0.x, q0.w));  // c0: m=4l,4l+1
                u0.y = h2u(__floats2half2_rn(q1.z, q2.y));  //     m=4l+2,4l+3
                u1.x = h2u(__floats2half2_rn(q0.y, q1.x));  // c1
                u1.y = h2u(__floats2half2_rn(q1.w, q2.z));
                u2.x = h2u(__floats2half2_rn(q0.z, q1.y));  // c2
                u2.y = h2u(__floats2half2_rn(q2.x, q2.w));
                *(uint2*)(dst0 + off) = u0;
                *(uint2*)(dst1 + off) = u1;
                *(uint2*)(dst2 + off) = u2;
            }
            __syncwarp();
            __threadfence();
            if (lane == 0)
                asm volatile("st.release.gpu.global.b32 [%0], %1;"
                             :: "l"(&g_flag[t]), "r"(1) : "memory");
        }
    }

    // ================= consumer loop (all warps; R11-proven body) ==========
    for (;;) {
        int s = 0;
        if (lane == 0) s = atomicAdd(&g_ctr, 1);
        s = __shfl_sync(0xFFFFFFFFu, s, 0);
        if (s >= total) break;

        const long row0g = (long)s * 16;
        const int t = s >> 3, rb = s & 7;
        const __half* xvBase = &g_xv[((long)t * 3) * 128 * PA + (long)rb * 16 * PA];

        // wait for producer (acquire); in-order streams make spins rare
        if (lane == 0) {
            for (;;) {
                int f;
                asm volatile("ld.acquire.gpu.global.b32 %0, [%1];"
                             : "=r"(f) : "l"(&g_flag[t]) : "memory");
                if (f) break;
                __nanosleep(128);
            }
        }
        __syncwarp();

        // ---- stage x_s (coalesced 512B rows, warp-local) ----
        #pragma unroll 4
        for (int it = 0; it < 16; ++it) {
            long grow = row0g + it;
            bool ok = grow < N;
            const float4* p = (const float4*)(x + grow * DIN);
            float4 v = ok ? p[lane] : make_float4(0, 0, 0, 0);
            uint2 u;
            u.x = h2u(__floats2half2_rn(v.x, v.y));
            u.y = h2u(__floats2half2_rn(v.z, v.w));
            *(uint2*)(warpBufP + (it * PA + lane * 4) * 2) = u;
        }
        __syncwarp();

        uint32_t af[32];
        ldsmA(af, aOff);               // x_s fragments -> regs; buffer free
        __syncwarp();
        cp_warp(warpBuf, xvBase, lane);   // prefetch ch0
        CP_COMMIT();

        // ---- gates: sigmoid(h_s[:,128:]) -> registers ----
        uint32_t gfa[16], gfb[16];
        #pragma unroll
        for (int h = 0; h < 2; ++h) {
            float acc[8][4] = {};
            gemm_rA4(acc, af, bG + h * 128, PB * 2);
            #pragma unroll
            for (int tt = 0; tt < 8; ++tt) {
                gfa[h * 8 + tt] = h2u(__floats2half2_rn(sigf(INV * acc[tt][0]),
                                                        sigf(INV * acc[tt][1])));
                gfb[h * 8 + tt] = h2u(__floats2half2_rn(sigf(INV * acc[tt][2]),
                                                        sigf(INV * acc[tt][3])));
            }
        }

        // ---- act: silu(h_s[:,:128]) -> A-fragments ----
        uint32_t afrag[32];
        #pragma unroll
        for (int h = 0; h < 2; ++h) {
            float acc[8][4] = {};
            gemm_rA4(acc, af, bA + h * 128, PB * 2);
            #pragma unroll
            for (int tt = 0; tt < 8; tt += 2) {
                int kb = h * 4 + (tt >> 1);
                float a0 = INV * acc[tt][0],     a1 = INV * acc[tt][1];
                float a2 = INV * acc[tt][2],     a3 = INV * acc[tt][3];
                float a4 = INV * acc[tt + 1][0], a5 = INV * acc[tt + 1][1];
                float a6 = INV * acc[tt + 1][2], a7 = INV * acc[tt + 1][3];
                a0 *= sigf(a0); a1 *= sigf(a1); a2 *= sigf(a2); a3 *= sigf(a3);
                a4 *= sigf(a4); a5 *= sigf(a5); a6 *= sigf(a6); a7 *= sigf(a7);
                afrag[4 * kb + 0] = h2u(__floats2half2_rn(a0, a1));
                afrag[4 * kb + 1] = h2u(__floats2half2_rn(a2, a3));
                afrag[4 * kb + 2] = h2u(__floats2half2_rn(a4, a5));
                afrag[4 * kb + 3] = h2u(__floats2half2_rn(a6, a7));
            }
        }

        // ---- L2-s; write out_s ----
        {
            float acc2[2][4] = {};
            gemm_rA1(acc2, afrag, bOffS, PW2 * 2);
            long gr0 = row0g + (lane >> 2), gr1 = gr0 + 8;
            if (gr0 < N) {
                *(float2*)&out[gr0 * 64 + cpair]     = make_float2(INV * acc2[0][0], INV * acc2[0][1]);
                *(float2*)&out[gr0 * 64 + cpair + 8] = make_float2(INV * acc2[1][0], INV * acc2[1][1]);
            }
            if (gr1 < N) {
                *(float2*)&out[gr1 * 64 + cpair]     = make_float2(INV * acc2[0][2], INV * acc2[0][3]);
                *(float2*)&out[gr1 * 64 + cpair + 8] = make_float2(INV * acc2[1][2], INV * acc2[1][3]);
            }
        }

        // ---- per-channel: G1-v -> gate (regs) -> L2-v ----
        float vout[24];
        #define VOUT(r, g, k, c) ((((r) * 2 + (g)) * 2 + (k)) * 3 + (c))
        #pragma unroll
        for (int c = 0; c < 3; ++c) {
            CP_WAIT(0);                 // channel c landed
            __syncwarp();
            ldsmA(af, aOff);
            __syncwarp();
            if (c < 2) {                // prefetch channel c+1
                cp_warp(warpBuf, xvBase + (long)(c + 1) * 128 * PA, lane);
                CP_COMMIT();
            }

            #pragma unroll
            for (int h = 0; h < 2; ++h) {
                float acc[8][4] = {};
                gemm_rA4(acc, af, bV + h * 128, PB * 2);
                #pragma unroll
                for (int tt = 0; tt < 8; tt += 2) {
                    int kb = h * 4 + (tt >> 1);
                    float2 g00 = __half22float2(*(__half2*)&gfa[h * 8 + tt]);
                    float2 g01 = __half22float2(*(__half2*)&gfb[h * 8 + tt]);
                    float2 g10 = __half22float2(*(__half2*)&gfa[h * 8 + tt + 1]);
                    float2 g11 = __half22float2(*(__half2*)&gfb[h * 8 + tt + 1]);
                    float a0 = INV * acc[tt][0] * g00.x,     a1 = INV * acc[tt][1] * g00.y;
                    float a2 = INV * acc[tt][2] * g01.x,     a3 = INV * acc[tt][3] * g01.y;
                    float a4 = INV * acc[tt + 1][0] * g10.x, a5 = INV * acc[tt + 1][1] * g10.y;
                    float a6 = INV * acc[tt + 1][2] * g11.x, a7 = INV * acc[tt + 1][3] * g11.y;
                    afrag[4 * kb + 0] = h2u(__floats2half2_rn(a0, a1));
                    afrag[4 * kb + 1] = h2u(__floats2half2_rn(a2, a3));
                    afrag[4 * kb + 2] = h2u(__floats2half2_rn(a4, a5));
                    afrag[4 * kb + 3] = h2u(__floats2half2_rn(a6, a7));
                }
            }
            {
                float acc2[2][4] = {};
                gemm_rA1(acc2, afrag, bOffV, PW2 * 2);
                vout[VOUT(0, 0, 0, c)] = INV * acc2[0][0];
                vout[VOUT(0, 0, 1, c)] = INV * acc2[0][1];
                vout[VOUT(1, 0, 0, c)] = INV * acc2[0][2];
                vout[VOUT(1, 0, 1, c)] = INV * acc2[0][3];
                vout[VOUT(0, 1, 0, c)] = INV * acc2[1][0];
                vout[VOUT(0, 1, 1, c)] = INV * acc2[1][1];
                vout[VOUT(1, 1, 0, c)] = INV * acc2[1][2];
                vout[VOUT(1, 1, 1, c)] = INV * acc2[1][3];
            }
        }

        // ---- write out_v ----
        #pragma unroll
        for (int r = 0; r < 2; ++r) {
            long gr = row0g + (lane >> 2) + r * 8;
            if (gr < N) {
                float* op = out + gr * 64 + 16;
                #pragma unroll
                for (int g = 0; g < 2; ++g) {
                    int kb = cpair + 8 * g;
                    float* q = op + kb * 3;
                    *(float2*)(q + 0) = make_float2(vout[VOUT(r, g, 0, 0)], vout[VOUT(r, g, 0, 1)]);
                    *(float2*)(q + 2) = make_float2(vout[VOUT(r, g, 0, 2)], vout[VOUT(r, g, 1, 0)]);
                    *(float2*)(q + 4) = make_float2(vout[VOUT(r, g, 1, 1)], vout[VOUT(r, g, 1, 2)]);
                }
            }
        }
        #undef VOUT
    }
}

// ---------------------------------------------------------------- launch
extern "C" void kernel_launch(void* const* d_in, const int* in_sizes, int n_in,
                              void* d_out, int out_size) {
    const float* x   = (const float*)d_in[0];
    const float* w1s = (const float*)d_in[1];
    const float* w1v = (const float*)d_in[2];
    const float* w2s = (const float*)d_in[3];
    const float* w2v = (const float*)d_in[4];
    float* out = (float*)d_out;

    const int N = in_sizes[0] / DIN;

    prep_w<<<132, 256>>>(w1s, w1v, w2s, w2v);

    cudaFuncSetAttribute(nlro, cudaFuncAttributeMaxDynamicSharedMemorySize,
                         SMEM_BYTES);
    nlro<<<NSM, THREADS, SMEM_BYTES>>>(x, out, N);
}

// round 15
// speedup vs baseline: 1.7010x; 1.2225x over previous
#include <cuda_runtime.h>
#include <cuda_fp16.h>
#include <cstdint>

// Fused NonLinearReadoutLayer via mma.sync.m16n8k16 (fp16 in, fp32 accum).
// Round 15: unified work queue in one persistent kernel. Task ids < tiles:
// produce a v-channel tile into g_xv (flag-released). Task ids >= tiles:
// consume a 16-row strip (R11-proven body: cp.async channel prefetch,
// register gates, warp-local everything). Counter order guarantees all
// production is in flight before any consumption task is issued.

#define DIN     512
#define THREADS 512
#define NSM     152
#define MAX_TILES 1564

#define PA  136   // halves
#define PB  136
#define PW2 40

// smem layout (bytes)
#define OFF_WG  0u          // w1s[1] (gates B)     34816
#define OFF_WA  34816u      // w1s[0] (act B)       34816
#define OFF_WV  69632u      // w1v                  34816
#define OFF_W2  104448u     // w2s|w2v              10240
#define OFF_AW  114688u     // 16 per-warp A buffers, 4352 B each
#define SMEM_BYTES 184320u

__device__ __align__(16) __half g_w1s[2][128 * PB];
__device__ __align__(16) __half g_w1v[128 * PB];
__device__ __align__(16) __half g_w2[128 * PW2];
__device__ __align__(16) __half g_xv[(long)MAX_TILES * 3 * 128 * PA];
__device__ int g_ctr;       // unified task counter
__device__ int g_flag[MAX_TILES];

// ---------------------------------------------------------------- helpers
__device__ __forceinline__ uint32_t smem_u32(const void* p) {
    uint32_t a;
    asm("{ .reg .u64 t; cvta.to.shared.u64 t, %1; cvt.u32.u64 %0, t; }"
        : "=r"(a) : "l"(p));
    return a;
}
__device__ __forceinline__ uint32_t h2u(__half2 h) {
    return *reinterpret_cast<uint32_t*>(&h);
}
__device__ __forceinline__ float sigf(float x) {
    return __fdividef(1.0f, 1.0f + __expf(-x));
}
#define CP16(d, s) \
    asm volatile("cp.async.cg.shared.global [%0], [%1], 16;" \
                 :: "r"(d), "l"(s))
#define CP_COMMIT() asm volatile("cp.async.commit_group;" ::: "memory")
#define CP_WAIT(n)  asm volatile("cp.async.wait_group %0;" :: "n"(n) : "memory")

__device__ __forceinline__ void cp_bulk(uint32_t dst, const void* src, int n16,
                                        int tid) {
    const char* s = (const char*)src;
    for (int i = tid; i < n16; i += THREADS) CP16(dst + i * 16, s + (long)i * 16);
}
__device__ __forceinline__ void cp_warp(uint32_t dst, const void* src, int lane) {
    const char* s = (const char*)src;
    #pragma unroll
    for (int i = lane; i < 272; i += 32) CP16(dst + i * 16, s + (long)i * 16);
}

__device__ __forceinline__ void ldsm4(uint32_t* r, uint32_t addr) {
    asm volatile("ldmatrix.sync.aligned.m8n8.x4.shared.b16 {%0,%1,%2,%3}, [%4];"
                 : "=r"(r[0]), "=r"(r[1]), "=r"(r[2]), "=r"(r[3]) : "r"(addr));
}
__device__ __forceinline__ void ldsm4t(uint32_t* r, uint32_t addr) {
    asm volatile("ldmatrix.sync.aligned.m8n8.x4.trans.shared.b16 {%0,%1,%2,%3}, [%4];"
                 : "=r"(r[0]), "=r"(r[1]), "=r"(r[2]), "=r"(r[3]) : "r"(addr));
}
__device__ __forceinline__ void mma16816(float* c, const uint32_t* a, const uint32_t* b) {
    asm volatile(
        "mma.sync.aligned.m16n8k16.row.col.f32.f16.f16.f32 "
        "{%0,%1,%2,%3}, {%4,%5,%6,%7}, {%8,%9}, {%0,%1,%2,%3};"
        : "+f"(c[0]), "+f"(c[1]), "+f"(c[2]), "+f"(c[3])
        : "r"(a[0]), "r"(a[1]), "r"(a[2]), "r"(a[3]), "r"(b[0]), "r"(b[1]));
}
__device__ __forceinline__ void ldsmA(uint32_t* af, uint32_t aAddr) {
    #pragma unroll
    for (int k = 0; k < 8; ++k) ldsm4(af + 4 * k, aAddr + k * 32);
}
__device__ __forceinline__ void gemm_rA4(float (*acc)[4], const uint32_t* af,
                                         uint32_t bAddr, uint32_t pbB) {
    #pragma unroll
    for (int k = 0; k < 8; ++k) {
        #pragma unroll
        for (int g = 0; g < 4; ++g) {
            uint32_t b[4];
            ldsm4t(b, bAddr + k * 16 * pbB + g * 32);
            mma16816(acc[2 * g],     af + 4 * k, b);
            mma16816(acc[2 * g + 1], af + 4 * k, b + 2);
        }
    }
}
__device__ __forceinline__ void gemm_rA1(float (*acc)[4], const uint32_t* af,
                                         uint32_t bAddr, uint32_t pbB) {
    #pragma unroll
    for (int k = 0; k < 8; ++k) {
        uint32_t b[4];
        ldsm4t(b, bAddr + k * 16 * pbB);
        mma16816(acc[0], af + 4 * k, b);
        mma16816(acc[1], af + 4 * k, b + 2);
    }
}

// ---------------------------------------------------------------- prep (weights + reset)
__global__ void prep_w(const float* __restrict__ w1s, const float* __restrict__ w1v,
                       const float* __restrict__ w2s, const float* __restrict__ w2v) {
    int idx = blockIdx.x * blockDim.x + threadIdx.x;
    int stride = gridDim.x * blockDim.x;
    if (idx == 0) g_ctr = 0;
    for (int i = idx; i < MAX_TILES; i += stride) g_flag[i] = 0;
    for (int i = idx; i < 2 * 128 * 128; i += stride) {
        int h = i >> 14, k = (i >> 7) & 127, n = i & 127;
        g_w1s[h][k * PB + n] = __float2half_rn(w1s[k * 256 + h * 128 + n]);
    }
    for (int i = idx; i < 128 * 128; i += stride)
        g_w1v[(i >> 7) * PB + (i & 127)] = __float2half_rn(w1v[i]);
    for (int i = idx; i < 128 * 16; i += stride) {
        int k = i >> 4, n = i & 15;
        g_w2[k * PW2 + n]      = __float2half_rn(w2s[i]);
        g_w2[k * PW2 + 16 + n] = __float2half_rn(w2v[i]);
    }
}

// ---------------------------------------------------------------- main (persistent)
__global__ void __launch_bounds__(THREADS, 1)
nlro(const float* __restrict__ x, float* __restrict__ out, int N) {
    extern __shared__ char sm[];
    const uint32_t smb = smem_u32(sm);
    const int tid = threadIdx.x, lane = tid & 31, wid = tid >> 5;
    const float INV = 0.08838834764831845f;

    const int cpair = 2 * (lane & 3);
    const int l16 = lane & 15, lhi = lane >> 4;

    const uint32_t warpBuf = smb + OFF_AW + wid * 4352u;
    char* warpBufP = sm + OFF_AW + wid * 4352u;
    const uint32_t aOff = warpBuf + (l16 * PA + lhi * 8) * 2;
    const uint32_t bG   = smb + OFF_WG + (l16 * PB + lhi * 8) * 2;
    const uint32_t bA   = smb + OFF_WA + (l16 * PB + lhi * 8) * 2;
    const uint32_t bV   = smb + OFF_WV + (l16 * PB + lhi * 8) * 2;
    const uint32_t bOffS = smb + OFF_W2 + (l16 * PW2 + lhi * 8) * 2;
    const uint32_t bOffV = bOffS + 32;

    // ---- one-time weight residency (only CTA barrier in the kernel) ----
    cp_bulk(smb + OFF_WG, &g_w1s[1][0], 2176, tid);
    cp_bulk(smb + OFF_WA, &g_w1s[0][0], 2176, tid);
    cp_bulk(smb + OFF_WV, g_w1v, 2176, tid);
    cp_bulk(smb + OFF_W2, g_w2, 640, tid);
    CP_COMMIT();
    CP_WAIT(0);
    __syncthreads();

    const int tiles = (N + 127) >> 7;
    const int total = (N + 15) >> 4;
    const int ntask = tiles + total;

    for (;;) {
        int id = 0;
        if (lane == 0) id = atomicAdd(&g_ctr, 1);
        id = __shfl_sync(0xFFFFFFFFu, id, 0);
        if (id >= ntask) break;

        if (id < tiles) {
            // ================= PRODUCE tile id =================
            const int t = id;
            const long rbase = (long)t * 128;
            __half* dst0 = &g_xv[((long)t * 3 + 0) * 128 * PA];
            __half* dst1 = &g_xv[((long)t * 3 + 1) * 128 * PA];
            __half* dst2 = &g_xv[((long)t * 3 + 2) * 128 * PA];
            #pragma unroll 4
            for (int row = 0; row < 128; ++row) {
                long grow = rbase + row;
                bool ok = grow < N;
                const float4* p = (const float4*)(x + grow * DIN + 128) + 3 * lane;
                float4 q0 = ok ? p[0] : make_float4(0, 0, 0, 0);
                float4 q1 = ok ? p[1] : make_float4(0, 0, 0, 0);
                float4 q2 = ok ? p[2] : make_float4(0, 0, 0, 0);
                uint32_t off = (uint32_t)row * PA + lane * 4;
                uint2 u0, u1, u2;
                u0.x = h2u(__floats2half2_rn(q0.x, q0.w));  // c0: m=4l,4l+1
                u0.y = h2u(__floats2half2_rn(q1.z, q2.y));  //     m=4l+2,4l+3
                u1.x = h2u(__floats2half2_rn(q0.y, q1.x));  // c1
                u1.y = h2u(__floats2half2_rn(q1.w, q2.z));
                u2.x = h2u(__floats2half2_rn(q0.z, q1.y));  // c2
                u2.y = h2u(__floats2half2_rn(q2.x, q2.w));
                *(uint2*)(dst0 + off) = u0;
                *(uint2*)(dst1 + off) = u1;
                *(uint2*)(dst2 + off) = u2;
            }
            __syncwarp();
            __threadfence();
            if (lane == 0)
                asm volatile("st.release.gpu.global.b32 [%0], %1;"
                             :: "l"(&g_flag[t]), "r"(1) : "memory");
            continue;
        }

        // ================= CONSUME strip (id - tiles) =================
        const int s = id - tiles;
        const long row0g = (long)s * 16;
        const int t = s >> 3, rb = s & 7;
        const __half* xvBase = &g_xv[((long)t * 3) * 128 * PA + (long)rb * 16 * PA];

        // ---- stage x_s (useful work before any flag wait) ----
        #pragma unroll 4
        for (int it = 0; it < 16; ++it) {
            long grow = row0g + it;
            bool ok = grow < N;
            const float4* p = (const float4*)(x + grow * DIN);
            float4 v = ok ? p[lane] : make_float4(0, 0, 0, 0);
            uint2 u;
            u.x = h2u(__floats2half2_rn(v.x, v.y));
            u.y = h2u(__floats2half2_rn(v.z, v.w));
            *(uint2*)(warpBufP + (it * PA + lane * 4) * 2) = u;
        }
        __syncwarp();

        uint32_t af[32];
        ldsmA(af, aOff);               // x_s fragments -> regs; buffer free
        __syncwarp();

        // wait for producer of tile t (acquire), then prefetch ch0
        if (lane == 0) {
            for (;;) {
                int f;
                asm volatile("ld.acquire.gpu.global.b32 %0, [%1];"
                             : "=r"(f) : "l"(&g_flag[t]) : "memory");
                if (f) break;
                __nanosleep(256);
            }
        }
        __syncwarp();
        cp_warp(warpBuf, xvBase, lane);   // prefetch ch0
        CP_COMMIT();

        // ---- gates: sigmoid(h_s[:,128:]) -> registers ----
        uint32_t gfa[16], gfb[16];
        #pragma unroll
        for (int h = 0; h < 2; ++h) {
            float acc[8][4] = {};
            gemm_rA4(acc, af, bG + h * 128, PB * 2);
            #pragma unroll
            for (int tt = 0; tt < 8; ++tt) {
                gfa[h * 8 + tt] = h2u(__floats2half2_rn(sigf(INV * acc[tt][0]),
                                                        sigf(INV * acc[tt][1])));
                gfb[h * 8 + tt] = h2u(__floats2half2_rn(sigf(INV * acc[tt][2]),
                                                        sigf(INV * acc[tt][3])));
            }
        }

        // ---- act: silu(h_s[:,:128]) -> A-fragments ----
        uint32_t afrag[32];
        #pragma unroll
        for (int h = 0; h < 2; ++h) {
            float acc[8][4] = {};
            gemm_rA4(acc, af, bA + h * 128, PB * 2);
            #pragma unroll
            for (int tt = 0; tt < 8; tt += 2) {
                int kb = h * 4 + (tt >> 1);
                float a0 = INV * acc[tt][0],     a1 = INV * acc[tt][1];
                float a2 = INV * acc[tt][2],     a3 = INV * acc[tt][3];
                float a4 = INV * acc[tt + 1][0], a5 = INV * acc[tt + 1][1];
                float a6 = INV * acc[tt + 1][2], a7 = INV * acc[tt + 1][3];
                a0 *= sigf(a0); a1 *= sigf(a1); a2 *= sigf(a2); a3 *= sigf(a3);
                a4 *= sigf(a4); a5 *= sigf(a5); a6 *= sigf(a6); a7 *= sigf(a7);
                afrag[4 * kb + 0] = h2u(__floats2half2_rn(a0, a1));
                afrag[4 * kb + 1] = h2u(__floats2half2_rn(a2, a3));
                afrag[4 * kb + 2] = h2u(__floats2half2_rn(a4, a5));
                afrag[4 * kb + 3] = h2u(__floats2half2_rn(a6, a7));
            }
        }

        // ---- L2-s; write out_s ----
        {
            float acc2[2][4] = {};
            gemm_rA1(acc2, afrag, bOffS, PW2 * 2);
            long gr0 = row0g + (lane >> 2), gr1 = gr0 + 8;
            if (gr0 < N) {
                *(float2*)&out[gr0 * 64 + cpair]     = make_float2(INV * acc2[0][0], INV * acc2[0][1]);
                *(float2*)&out[gr0 * 64 + cpair + 8] = make_float2(INV * acc2[1][0], INV * acc2[1][1]);
            }
            if (gr1 < N) {
                *(float2*)&out[gr1 * 64 + cpair]     = make_float2(INV * acc2[0][2], INV * acc2[0][3]);
                *(float2*)&out[gr1 * 64 + cpair + 8] = make_float2(INV * acc2[1][2], INV * acc2[1][3]);
            }
        }

        // ---- per-channel: G1-v -> gate (regs) -> L2-v ----
        float vout[24];
        #define VOUT(r, g, k, c) ((((r) * 2 + (g)) * 2 + (k)) * 3 + (c))
        #pragma unroll
        for (int c = 0; c < 3; ++c) {
            CP_WAIT(0);                 // channel c landed
            __syncwarp();
            ldsmA(af, aOff);
            __syncwarp();
            if (c < 2) {                // prefetch channel c+1
                cp_warp(warpBuf, xvBase + (long)(c + 1) * 128 * PA, lane);
                CP_COMMIT();
            }

            #pragma unroll
            for (int h = 0; h < 2; ++h) {
                float acc[8][4] = {};
                gemm_rA4(acc, af, bV + h * 128, PB * 2);
                #pragma unroll
                for (int tt = 0; tt < 8; tt += 2) {
                    int kb = h * 4 + (tt >> 1);
                    float2 g00 = __half22float2(*(__half2*)&gfa[h * 8 + tt]);
                    float2 g01 = __half22float2(*(__half2*)&gfb[h * 8 + tt]);
                    float2 g10 = __half22float2(*(__half2*)&gfa[h * 8 + tt + 1]);
                    float2 g11 = __half22float2(*(__half2*)&gfb[h * 8 + tt + 1]);
                    float a0 = INV * acc[tt][0] * g00.x,     a1 = INV * acc[tt][1] * g00.y;
                    float a2 = INV * acc[tt][2] * g01.x,     a3 = INV * acc[tt][3] * g01.y;
                    float a4 = INV * acc[tt + 1][0] * g10.x, a5 = INV * acc[tt + 1][1] * g10.y;
                    float a6 = INV * acc[tt + 1][2] * g11.x, a7 = INV * acc[tt + 1][3] * g11.y;
                    afrag[4 * kb + 0] = h2u(__floats2half2_rn(a0, a1));
                    afrag[4 * kb + 1] = h2u(__floats2half2_rn(a2, a3));
                    afrag[4 * kb + 2] = h2u(__floats2half2_rn(a4, a5));
                    afrag[4 * kb + 3] = h2u(__floats2half2_rn(a6, a7));
                }
            }
            {
                float acc2[2][4] = {};
                gemm_rA1(acc2, afrag, bOffV, PW2 * 2);
                vout[VOUT(0, 0, 0, c)] = INV * acc2[0][0];
                vout[VOUT(0, 0, 1, c)] = INV * acc2[0][1];
                vout[VOUT(1, 0, 0, c)] = INV * acc2[0][2];
                vout[VOUT(1, 0, 1, c)] = INV * acc2[0][3];
                vout[VOUT(0, 1, 0, c)] = INV * acc2[1][0];
                vout[VOUT(0, 1, 1, c)] = INV * acc2[1][1];
                vout[VOUT(1, 1, 0, c)] = INV * acc2[1][2];
                vout[VOUT(1, 1, 1, c)] = INV * acc2[1][3];
            }
        }

        // ---- write out_v ----
        #pragma unroll
        for (int r = 0; r < 2; ++r) {
            long gr = row0g + (lane >> 2) + r * 8;
            if (gr < N) {
                float* op = out + gr * 64 + 16;
                #pragma unroll
                for (int g = 0; g < 2; ++g) {
                    int kb = cpair + 8 * g;
                    float* q = op + kb * 3;
                    *(float2*)(q + 0) = make_float2(vout[VOUT(r, g, 0, 0)], vout[VOUT(r, g, 0, 1)]);
                    *(float2*)(q + 2) = make_float2(vout[VOUT(r, g, 0, 2)], vout[VOUT(r, g, 1, 0)]);
                    *(float2*)(q + 4) = make_float2(vout[VOUT(r, g, 1, 1)], vout[VOUT(r, g, 1, 2)]);
                }
            }
        }
        #undef VOUT
    }
}

// ---------------------------------------------------------------- launch
extern "C" void kernel_launch(void* const* d_in, const int* in_sizes, int n_in,
                              void* d_out, int out_size) {
    const float* x   = (const float*)d_in[0];
    const float* w1s = (const float*)d_in[1];
    const float* w1v = (const float*)d_in[2];
    const float* w2s = (const float*)d_in[3];
    const float* w2v = (const float*)d_in[4];
    float* out = (float*)d_out;

    const int N = in_sizes[0] / DIN;

    prep_w<<<132, 256>>>(w1s, w1v, w2s, w2v);

    cudaFuncSetAttribute(nlro, cudaFuncAttributeMaxDynamicSharedMemorySize,
                         SMEM_BYTES);
    nlro<<<NSM, THREADS, SMEM_BYTES>>>(x, out, N);
}

// round 16
// speedup vs baseline: 1.8507x; 1.0880x over previous
#include <cuda_runtime.h>
#include <cuda_fp16.h>
#include <cstdint>

// Fused NonLinearReadoutLayer via mma.sync.m16n8k16 (fp16 in, fp32 accum).
// Round 16: JIT-interleaved unified work queue. Lead window W produce-tasks,
// then groups of 9 = 1 produce (tile W+g) + 8 strips (tile g): production
// leads consumption by W tiles -> g_xv stays L2-resident; production DRAM
// spread across the kernel. Consumer waits on the tile flag only after
// gates/act/L2-s (which need only x_s).

#define DIN     512
#define THREADS 512
#define NSM     152
#define MAX_TILES 1564
#define LEAD    384

#define PA  136   // halves
#define PB  136
#define PW2 40

// smem layout (bytes)
#define OFF_WG  0u          // w1s[1] (gates B)     34816
#define OFF_WA  34816u      // w1s[0] (act B)       34816
#define OFF_WV  69632u      // w1v                  34816
#define OFF_W2  104448u     // w2s|w2v              10240
#define OFF_AW  114688u     // 16 per-warp A buffers, 4352 B each
#define SMEM_BYTES 184320u

__device__ __align__(16) __half g_w1s[2][128 * PB];
__device__ __align__(16) __half g_w1v[128 * PB];
__device__ __align__(16) __half g_w2[128 * PW2];
__device__ __align__(16) __half g_xv[(long)MAX_TILES * 3 * 128 * PA];
__device__ int g_ctr;       // unified task counter
__device__ int g_flag[MAX_TILES];

// ---------------------------------------------------------------- helpers
__device__ __forceinline__ uint32_t smem_u32(const void* p) {
    uint32_t a;
    asm("{ .reg .u64 t; cvta.to.shared.u64 t, %1; cvt.u32.u64 %0, t; }"
        : "=r"(a) : "l"(p));
    return a;
}
__device__ __forceinline__ uint32_t h2u(__half2 h) {
    return *reinterpret_cast<uint32_t*>(&h);
}
__device__ __forceinline__ float sigf(float x) {
    return __fdividef(1.0f, 1.0f + __expf(-x));
}
#define CP16(d, s) \
    asm volatile("cp.async.cg.shared.global [%0], [%1], 16;" \
                 :: "r"(d), "l"(s))
#define CP_COMMIT() asm volatile("cp.async.commit_group;" ::: "memory")
#define CP_WAIT(n)  asm volatile("cp.async.wait_group %0;" :: "n"(n) : "memory")

__device__ __forceinline__ void cp_bulk(uint32_t dst, const void* src, int n16,
                                        int tid) {
    const char* s = (const char*)src;
    for (int i = tid; i < n16; i += THREADS) CP16(dst + i * 16, s + (long)i * 16);
}
__device__ __forceinline__ void cp_warp(uint32_t dst, const void* src, int lane) {
    const char* s = (const char*)src;
    #pragma unroll
    for (int i = lane; i < 272; i += 32) CP16(dst + i * 16, s + (long)i * 16);
}

__device__ __forceinline__ void ldsm4(uint32_t* r, uint32_t addr) {
    asm volatile("ldmatrix.sync.aligned.m8n8.x4.shared.b16 {%0,%1,%2,%3}, [%4];"
                 : "=r"(r[0]), "=r"(r[1]), "=r"(r[2]), "=r"(r[3]) : "r"(addr));
}
__device__ __forceinline__ void ldsm4t(uint32_t* r, uint32_t addr) {
    asm volatile("ldmatrix.sync.aligned.m8n8.x4.trans.shared.b16 {%0,%1,%2,%3}, [%4];"
                 : "=r"(r[0]), "=r"(r[1]), "=r"(r[2]), "=r"(r[3]) : "r"(addr));
}
__device__ __forceinline__ void mma16816(float* c, const uint32_t* a, const uint32_t* b) {
    asm volatile(
        "mma.sync.aligned.m16n8k16.row.col.f32.f16.f16.f32 "
        "{%0,%1,%2,%3}, {%4,%5,%6,%7}, {%8,%9}, {%0,%1,%2,%3};"
        : "+f"(c[0]), "+f"(c[1]), "+f"(c[2]), "+f"(c[3])
        : "r"(a[0]), "r"(a[1]), "r"(a[2]), "r"(a[3]), "r"(b[0]), "r"(b[1]));
}
__device__ __forceinline__ void ldsmA(uint32_t* af, uint32_t aAddr) {
    #pragma unroll
    for (int k = 0; k < 8; ++k) ldsm4(af + 4 * k, aAddr + k * 32);
}
__device__ __forceinline__ void gemm_rA4(float (*acc)[4], const uint32_t* af,
                                         uint32_t bAddr, uint32_t pbB) {
    #pragma unroll
    for (int k = 0; k < 8; ++k) {
        #pragma unroll
        for (int g = 0; g < 4; ++g) {
            uint32_t b[4];
            ldsm4t(b, bAddr + k * 16 * pbB + g * 32);
            mma16816(acc[2 * g],     af + 4 * k, b);
            mma16816(acc[2 * g + 1], af + 4 * k, b + 2);
        }
    }
}
__device__ __forceinline__ void gemm_rA1(float (*acc)[4], const uint32_t* af,
                                         uint32_t bAddr, uint32_t pbB) {
    #pragma unroll
    for (int k = 0; k < 8; ++k) {
        uint32_t b[4];
        ldsm4t(b, bAddr + k * 16 * pbB);
        mma16816(acc[0], af + 4 * k, b);
        mma16816(acc[1], af + 4 * k, b + 2);
    }
}

// ---------------------------------------------------------------- prep (weights + reset)
__global__ void prep_w(const float* __restrict__ w1s, const float* __restrict__ w1v,
                       const float* __restrict__ w2s, const float* __restrict__ w2v) {
    int idx = blockIdx.x * blockDim.x + threadIdx.x;
    int stride = gridDim.x * blockDim.x;
    if (idx == 0) g_ctr = 0;
    for (int i = idx; i < MAX_TILES; i += stride) g_flag[i] = 0;
    for (int i = idx; i < 2 * 128 * 128; i += stride) {
        int h = i >> 14, k = (i >> 7) & 127, n = i & 127;
        g_w1s[h][k * PB + n] = __float2half_rn(w1s[k * 256 + h * 128 + n]);
    }
    for (int i = idx; i < 128 * 128; i += stride)
        g_w1v[(i >> 7) * PB + (i & 127)] = __float2half_rn(w1v[i]);
    for (int i = idx; i < 128 * 16; i += stride) {
        int k = i >> 4, n = i & 15;
        g_w2[k * PW2 + n]      = __float2half_rn(w2s[i]);
        g_w2[k * PW2 + 16 + n] = __float2half_rn(w2v[i]);
    }
}

// ---------------------------------------------------------------- main (persistent)
__global__ void __launch_bounds__(THREADS, 1)
nlro(const float* __restrict__ x, float* __restrict__ out, int N) {
    extern __shared__ char sm[];
    const uint32_t smb = smem_u32(sm);
    const int tid = threadIdx.x, lane = tid & 31, wid = tid >> 5;
    const float INV = 0.08838834764831845f;

    const int cpair = 2 * (lane & 3);
    const int l16 = lane & 15, lhi = lane >> 4;

    const uint32_t warpBuf = smb + OFF_AW + wid * 4352u;
    char* warpBufP = sm + OFF_AW + wid * 4352u;
    const uint32_t aOff = warpBuf + (l16 * PA + lhi * 8) * 2;
    const uint32_t bG   = smb + OFF_WG + (l16 * PB + lhi * 8) * 2;
    const uint32_t bA   = smb + OFF_WA + (l16 * PB + lhi * 8) * 2;
    const uint32_t bV   = smb + OFF_WV + (l16 * PB + lhi * 8) * 2;
    const uint32_t bOffS = smb + OFF_W2 + (l16 * PW2 + lhi * 8) * 2;
    const uint32_t bOffV = bOffS + 32;

    // ---- one-time weight residency (only CTA barrier in the kernel) ----
    cp_bulk(smb + OFF_WG, &g_w1s[1][0], 2176, tid);
    cp_bulk(smb + OFF_WA, &g_w1s[0][0], 2176, tid);
    cp_bulk(smb + OFF_WV, g_w1v, 2176, tid);
    cp_bulk(smb + OFF_W2, g_w2, 640, tid);
    CP_COMMIT();
    CP_WAIT(0);
    __syncthreads();

    const int tiles = (N + 127) >> 7;
    const int total = (N + 15) >> 4;
    const int W = (LEAD < tiles) ? LEAD : tiles;
    const int ntask = W + 9 * tiles;

    for (;;) {
        int id = 0;
        if (lane == 0) id = atomicAdd(&g_ctr, 1);
        id = __shfl_sync(0xFFFFFFFFu, id, 0);
        if (id >= ntask) break;

        // ---- decode task ----
        int ptile = -1, s = -1;
        if (id < W) {
            ptile = id;
        } else {
            int j = id - W, g = j / 9, r = j - g * 9;
            if (r == 0) {
                int t2 = W + g;
                if (t2 < tiles) ptile = t2; else continue;
            } else {
                s = g * 8 + (r - 1);
                if (s >= total) continue;
            }
        }

        if (ptile >= 0) {
            // ================= PRODUCE tile ptile =================
            const int t = ptile;
            const long rbase = (long)t * 128;
            __half* dst0 = &g_xv[((long)t * 3 + 0) * 128 * PA];
            __half* dst1 = &g_xv[((long)t * 3 + 1) * 128 * PA];
            __half* dst2 = &g_xv[((long)t * 3 + 2) * 128 * PA];
            #pragma unroll 4
            for (int row = 0; row < 128; ++row) {
                long grow = rbase + row;
                bool ok = grow < N;
                const float4* p = (const float4*)(x + grow * DIN + 128) + 3 * lane;
                float4 q0 = ok ? p[0] : make_float4(0, 0, 0, 0);
                float4 q1 = ok ? p[1] : make_float4(0, 0, 0, 0);
                float4 q2 = ok ? p[2] : make_float4(0, 0, 0, 0);
                uint32_t off = (uint32_t)row * PA + lane * 4;
                uint2 u0, u1, u2;
                u0.x = h2u(__floats2half2_rn(q0.x, q0.w));  // c0: m=4l,4l+1
                u0.y = h2u(__floats2half2_rn(q1.z, q2.y));  //     m=4l+2,4l+3
                u1.x = h2u(__floats2half2_rn(q0.y, q1.x));  // c1
                u1.y = h2u(__floats2half2_rn(q1.w, q2.z));
                u2.x = h2u(__floats2half2_rn(q0.z, q1.y));  // c2
                u2.y = h2u(__floats2half2_rn(q2.x, q2.w));
                *(uint2*)(dst0 + off) = u0;
                *(uint2*)(dst1 + off) = u1;
                *(uint2*)(dst2 + off) = u2;
            }
            __syncwarp();
            __threadfence();
            if (lane == 0)
                asm volatile("st.release.gpu.global.b32 [%0], %1;"
                             :: "l"(&g_flag[t]), "r"(1) : "memory");
            continue;
        }

        // ================= CONSUME strip s =================
        const long row0g = (long)s * 16;
        const int t = s >> 3, rb = s & 7;
        const __half* xvBase = &g_xv[((long)t * 3) * 128 * PA + (long)rb * 16 * PA];

        // ---- stage x_s (independent of v) ----
        #pragma unroll 4
        for (int it = 0; it < 16; ++it) {
            long grow = row0g + it;
            bool ok = grow < N;
            const float4* p = (const float4*)(x + grow * DIN);
            float4 v = ok ? p[lane] : make_float4(0, 0, 0, 0);
            uint2 u;
            u.x = h2u(__floats2half2_rn(v.x, v.y));
            u.y = h2u(__floats2half2_rn(v.z, v.w));
            *(uint2*)(warpBufP + (it * PA + lane * 4) * 2) = u;
        }
        __syncwarp();

        uint32_t af[32];
        ldsmA(af, aOff);               // x_s fragments -> regs; buffer free
        __syncwarp();

        // ---- early flag peek: prefetch ch0 now if tile already produced ----
        int ready;
        {
            int f = 0;
            if (lane == 0)
                asm volatile("ld.acquire.gpu.global.b32 %0, [%1];"
                             : "=r"(f) : "l"(&g_flag[t]) : "memory");
            ready = __shfl_sync(0xFFFFFFFFu, f, 0);
        }
        if (ready) {
            cp_warp(warpBuf, xvBase, lane);   // prefetch ch0
            CP_COMMIT();
        }

        // ---- gates: sigmoid(h_s[:,128:]) -> registers ----
        uint32_t gfa[16], gfb[16];
        #pragma unroll
        for (int h = 0; h < 2; ++h) {
            float acc[8][4] = {};
            gemm_rA4(acc, af, bG + h * 128, PB * 2);
            #pragma unroll
            for (int tt = 0; tt < 8; ++tt) {
                gfa[h * 8 + tt] = h2u(__floats2half2_rn(sigf(INV * acc[tt][0]),
                                                        sigf(INV * acc[tt][1])));
                gfb[h * 8 + tt] = h2u(__floats2half2_rn(sigf(INV * acc[tt][2]),
                                                        sigf(INV * acc[tt][3])));
            }
        }

        // ---- act: silu(h_s[:,:128]) -> A-fragments ----
        uint32_t afrag[32];
        #pragma unroll
        for (int h = 0; h < 2; ++h) {
            float acc[8][4] = {};
            gemm_rA4(acc, af, bA + h * 128, PB * 2);
            #pragma unroll
            for (int tt = 0; tt < 8; tt += 2) {
                int kb = h * 4 + (tt >> 1);
                float a0 = INV * acc[tt][0],     a1 = INV * acc[tt][1];
                float a2 = INV * acc[tt][2],     a3 = INV * acc[tt][3];
                float a4 = INV * acc[tt + 1][0], a5 = INV * acc[tt + 1][1];
                float a6 = INV * acc[tt + 1][2], a7 = INV * acc[tt + 1][3];
                a0 *= sigf(a0); a1 *= sigf(a1); a2 *= sigf(a2); a3 *= sigf(a3);
                a4 *= sigf(a4); a5 *= sigf(a5); a6 *= sigf(a6); a7 *= sigf(a7);
                afrag[4 * kb + 0] = h2u(__floats2half2_rn(a0, a1));
                afrag[4 * kb + 1] = h2u(__floats2half2_rn(a2, a3));
                afrag[4 * kb + 2] = h2u(__floats2half2_rn(a4, a5));
                afrag[4 * kb + 3] = h2u(__floats2half2_rn(a6, a7));
            }
        }

        // ---- L2-s; write out_s ----
        {
            float acc2[2][4] = {};
            gemm_rA1(acc2, afrag, bOffS, PW2 * 2);
            long gr0 = row0g + (lane >> 2), gr1 = gr0 + 8;
            if (gr0 < N) {
                *(float2*)&out[gr0 * 64 + cpair]     = make_float2(INV * acc2[0][0], INV * acc2[0][1]);
                *(float2*)&out[gr0 * 64 + cpair + 8] = make_float2(INV * acc2[1][0], INV * acc2[1][1]);
            }
            if (gr1 < N) {
                *(float2*)&out[gr1 * 64 + cpair]     = make_float2(INV * acc2[0][2], INV * acc2[0][3]);
                *(float2*)&out[gr1 * 64 + cpair + 8] = make_float2(INV * acc2[1][2], INV * acc2[1][3]);
            }
        }

        // ---- ensure tile produced; prefetch ch0 if not done earlier ----
        if (!ready) {
            if (lane == 0) {
                for (;;) {
                    int f;
                    asm volatile("ld.acquire.gpu.global.b32 %0, [%1];"
                                 : "=r"(f) : "l"(&g_flag[t]) : "memory");
                    if (f) break;
                    __nanosleep(256);
                }
            }
            __syncwarp();
            cp_warp(warpBuf, xvBase, lane);
            CP_COMMIT();
        }

        // ---- per-channel: G1-v -> gate (regs) -> L2-v ----
        float vout[24];
        #define VOUT(r, g, k, c) ((((r) * 2 + (g)) * 2 + (k)) * 3 + (c))
        #pragma unroll
        for (int c = 0; c < 3; ++c) {
            CP_WAIT(0);                 // channel c landed
            __syncwarp();
            ldsmA(af, aOff);
            __syncwarp();
            if (c < 2) {                // prefetch channel c+1
                cp_warp(warpBuf, xvBase + (long)(c + 1) * 128 * PA, lane);
                CP_COMMIT();
            }

            #pragma unroll
            for (int h = 0; h < 2; ++h) {
                float acc[8][4] = {};
                gemm_rA4(acc, af, bV + h * 128, PB * 2);
                #pragma unroll
                for (int tt = 0; tt < 8; tt += 2) {
                    int kb = h * 4 + (tt >> 1);
                    float2 g00 = __half22float2(*(__half2*)&gfa[h * 8 + tt]);
                    float2 g01 = __half22float2(*(__half2*)&gfb[h * 8 + tt]);
                    float2 g10 = __half22float2(*(__half2*)&gfa[h * 8 + tt + 1]);
                    float2 g11 = __half22float2(*(__half2*)&gfb[h * 8 + tt + 1]);
                    float a0 = INV * acc[tt][0] * g00.x,     a1 = INV * acc[tt][1] * g00.y;
                    float a2 = INV * acc[tt][2] * g01.x,     a3 = INV * acc[tt][3] * g01.y;
                    float a4 = INV * acc[tt + 1][0] * g10.x, a5 = INV * acc[tt + 1][1] * g10.y;
                    float a6 = INV * acc[tt + 1][2] * g11.x, a7 = INV * acc[tt + 1][3] * g11.y;
                    afrag[4 * kb + 0] = h2u(__floats2half2_rn(a0, a1));
                    afrag[4 * kb + 1] = h2u(__floats2half2_rn(a2, a3));
                    afrag[4 * kb + 2] = h2u(__floats2half2_rn(a4, a5));
                    afrag[4 * kb + 3] = h2u(__floats2half2_rn(a6, a7));
                }
            }
            {
                float acc2[2][4] = {};
                gemm_rA1(acc2, afrag, bOffV, PW2 * 2);
                vout[VOUT(0, 0, 0, c)] = INV * acc2[0][0];
                vout[VOUT(0, 0, 1, c)] = INV * acc2[0][1];
                vout[VOUT(1, 0, 0, c)] = INV * acc2[0][2];
                vout[VOUT(1, 0, 1, c)] = INV * acc2[0][3];
                vout[VOUT(0, 1, 0, c)] = INV * acc2[1][0];
                vout[VOUT(0, 1, 1, c)] = INV * acc2[1][1];
                vout[VOUT(1, 1, 0, c)] = INV * acc2[1][2];
                vout[VOUT(1, 1, 1, c)] = INV * acc2[1][3];
            }
        }

        // ---- write out_v ----
        #pragma unroll
        for (int r = 0; r < 2; ++r) {
            long gr = row0g + (lane >> 2) + r * 8;
            if (gr < N) {
                float* op = out + gr * 64 + 16;
                #pragma unroll
                for (int g = 0; g < 2; ++g) {
                    int kb = cpair + 8 * g;
                    float* q = op + kb * 3;
                    *(float2*)(q + 0) = make_float2(vout[VOUT(r, g, 0, 0)], vout[VOUT(r, g, 0, 1)]);
                    *(float2*)(q + 2) = make_float2(vout[VOUT(r, g, 0, 2)], vout[VOUT(r, g, 1, 0)]);
                    *(float2*)(q + 4) = make_float2(vout[VOUT(r, g, 1, 1)], vout[VOUT(r, g, 1, 2)]);
                }
            }
        }
        #undef VOUT
    }
}

// ---------------------------------------------------------------- launch
extern "C" void kernel_launch(void* const* d_in, const int* in_sizes, int n_in,
                              void* d_out, int out_size) {
    const float* x   = (const float*)d_in[0];
    const float* w1s = (const float*)d_in[1];
    const float* w1v = (const float*)d_in[2];
    const float* w2s = (const float*)d_in[3];
    const float* w2v = (const float*)d_in[4];
    float* out = (float*)d_out;

    const int N = in_sizes[0] / DIN;

    prep_w<<<132, 256>>>(w1s, w1v, w2s, w2v);

    cudaFuncSetAttribute(nlro, cudaFuncAttributeMaxDynamicSharedMemorySize,
                         SMEM_BYTES);
    nlro<<<NSM, THREADS, SMEM_BYTES>>>(x, out, N);
}